// round 9
// baseline (speedup 1.0000x reference)
#include <cuda_runtime.h>
#include <math.h>
#include <stdint.h>

// ---------------------------------------------------------------------------
// GWEModel: tokens -> embed -> 8x[rmsnorm, x+=0.1*(h@W.T), rmsnorm,
//           x+=0.1*silu(h@Wffn.T)] -> rmsnorm -> lm_head
// W / Wffn are GENERATED per call by a coord MLP over 64x64 blocks of 16x16.
// Everything is expressed as NT-SGEMMs (A[M,K] row-major, B[N,K] row-major).
// ---------------------------------------------------------------------------

#define D       1024
#define NLAYERS 8
#define VOCAB   32000
#define BSZ     16      // block size of generated matrix
#define GH      256     // generator hidden width
#define NFREQS  6
#define NTOK    4096    // 2 * 2048 tokens
#define NB      64      // D / BSZ blocks per side
#define NMAT    16      // 8 layers x 2 matrices
#define NROWS   (NMAT * NB * NB)   // 65536 generator rows
#define ENC_K   64      // 52 real features padded to 64 (for K%16==0)
#define EPSV    1.1920929e-07f

// ------------------------- scratch (device globals) ------------------------
__device__ float g_X[NTOK * D];            // 16 MB activations
__device__ float g_H[NTOK * D];            // 16 MB normed activations
__device__ float g_W[(size_t)NMAT * D * D];// 64 MB generated matrices
__device__ float g_G0[(size_t)NROWS * GH]; // 64 MB generator ping
__device__ float g_G1[(size_t)NROWS * GH]; // 64 MB generator pong
__device__ float g_ENC[(size_t)NROWS * ENC_K]; // 16 MB encoded coords
__device__ float g_W0P[GH * ENC_K];        // padded first-layer weight

// ------------------------------ tiny kernels -------------------------------
__global__ void k_gather(const int* __restrict__ tok,
                         const float* __restrict__ emb) {
    int t  = blockIdx.x;
    int tk = tok[t];
    const float4* src = (const float4*)(emb + (size_t)tk * D);
    float4*       dst = (float4*)(g_X + (size_t)t * D);
    dst[threadIdx.x] = src[threadIdx.x];   // 256 threads x float4 = 1024
}

__global__ void k_padw0(const float* __restrict__ w0) {
    int g = blockIdx.x;        // 0..255
    int f = threadIdx.x;       // 0..63
    g_W0P[g * ENC_K + f] = (f < 52) ? w0[g * 52 + f] : 0.0f;
}

// features: [x0..x3, sin(2^0 pi x)*4, cos(2^0 pi x)*4, sin(2^1 ...)...]
__global__ void k_encode() {
    int idx = blockIdx.x * blockDim.x + threadIdx.x;
    if (idx >= NROWS * ENC_K) return;
    int row = idx >> 6;
    int f   = idx & 63;
    float val = 0.0f;
    if (f < 52) {
        int   mat = row >> 12;           // 0..15
        int   blk = row & 4095;          // 0..4095
        float c0  = (float)(mat >> 1) * (1.0f / 7.0f);    // layer frac
        float c1  = (float)(blk >> 6) * (1.0f / 63.0f);   // row frac
        float c2  = (float)(blk & 63) * (1.0f / 63.0f);   // col frac
        float c3  = (mat & 1) ? 0.5f : 0.0f;              // func type
        float coords[4] = {c0, c1, c2, c3};
        if (f < 4) {
            val = coords[f];
        } else {
            int   q    = f - 4;
            int   g    = q >> 3;     // frequency index
            int   r    = q & 7;      // 0-3 sin, 4-7 cos
            float a    = (float)(1 << g) * 3.14159265358979f * coords[r & 3];
            val = (r >= 4) ? cosf(a) : sinf(a);
        }
    }
    g_ENC[idx] = val;
}

__global__ void k_rmsnorm(const float* __restrict__ x,
                          const float* __restrict__ w,
                          float* __restrict__ h) {
    int t   = threadIdx.x;   // 256
    int row = blockIdx.x;
    const float4* xr = (const float4*)(x + (size_t)row * D);
    float4 a = xr[t];
    float  s = a.x * a.x + a.y * a.y + a.z * a.z + a.w * a.w;
    #pragma unroll
    for (int o = 16; o > 0; o >>= 1) s += __shfl_xor_sync(0xffffffffu, s, o);
    __shared__ float sm[8];
    if ((t & 31) == 0) sm[t >> 5] = s;
    __syncthreads();
    float tot = 0.0f;
    #pragma unroll
    for (int i = 0; i < 8; i++) tot += sm[i];
    float inv = rsqrtf(tot * (1.0f / 1024.0f) + EPSV);
    float4 wv = ((const float4*)w)[t];
    float4 o;
    o.x = a.x * inv * wv.x; o.y = a.y * inv * wv.y;
    o.z = a.z * inv * wv.z; o.w = a.w * inv * wv.w;
    ((float4*)(h + (size_t)row * D))[t] = o;
}

// ------------------------------ SGEMM (NT) ---------------------------------
// C[M,N] = A[M,K] @ B[N,K]^T, 128x128 tile, BK=16, 256 threads, 8x8/thread.
enum { EPI_STORE = 0, EPI_SILU = 1, EPI_GENW = 2, EPI_RESID = 3, EPI_RESID_SILU = 4 };

__device__ __forceinline__ float siluf(float v) {
    return v / (1.0f + __expf(-v));
}

template <int EPI>
__global__ __launch_bounds__(256)
void k_sgemm(const float* __restrict__ A, const float* __restrict__ B,
             const float* __restrict__ bias, float* __restrict__ OUT,
             int M, int N, int K) {
    __shared__ float As[16][128];
    __shared__ float Bs[16][128];
    const int tid = threadIdx.x;
    const int tx  = tid & 15;      // 0..15 -> N
    const int ty  = tid >> 4;      // 0..15 -> M
    const int bm  = blockIdx.y * 128;
    const int bn  = blockIdx.x * 128;
    const float* Ab = A + (size_t)bm * K;
    const float* Bb = B + (size_t)bn * K;

    float acc[8][8];
    #pragma unroll
    for (int i = 0; i < 8; i++)
        #pragma unroll
        for (int j = 0; j < 8; j++) acc[i][j] = 0.0f;

    for (int k0 = 0; k0 < K; k0 += 16) {
        #pragma unroll
        for (int it = 0; it < 2; it++) {
            int idx = tid + it * 256;
            int r   = idx >> 2;            // 0..127 tile row
            int c   = (idx & 3) << 2;      // 0,4,8,12 k-offset
            float4 va = *(const float4*)(Ab + (size_t)r * K + k0 + c);
            As[c + 0][r] = va.x; As[c + 1][r] = va.y;
            As[c + 2][r] = va.z; As[c + 3][r] = va.w;
            float4 vb = *(const float4*)(Bb + (size_t)r * K + k0 + c);
            Bs[c + 0][r] = vb.x; Bs[c + 1][r] = vb.y;
            Bs[c + 2][r] = vb.z; Bs[c + 3][r] = vb.w;
        }
        __syncthreads();
        #pragma unroll
        for (int k = 0; k < 16; k++) {
            float ra[8], rb[8];
            *(float4*)(ra)     = *(const float4*)&As[k][ty * 8];
            *(float4*)(ra + 4) = *(const float4*)&As[k][ty * 8 + 4];
            *(float4*)(rb)     = *(const float4*)&Bs[k][tx * 8];
            *(float4*)(rb + 4) = *(const float4*)&Bs[k][tx * 8 + 4];
            #pragma unroll
            for (int i = 0; i < 8; i++)
                #pragma unroll
                for (int j = 0; j < 8; j++)
                    acc[i][j] = fmaf(ra[i], rb[j], acc[i][j]);
        }
        __syncthreads();
    }

    #pragma unroll
    for (int i = 0; i < 8; i++) {
        int m = bm + ty * 8 + i;
        #pragma unroll
        for (int j = 0; j < 8; j++) {
            int   n = bn + tx * 8 + j;
            float v = acc[i][j];
            if (EPI == EPI_STORE) {
                OUT[(size_t)m * N + n] = v;
            } else if (EPI == EPI_SILU) {
                OUT[(size_t)m * N + n] = siluf(v + bias[n]);
            } else if (EPI == EPI_GENW) {
                v += bias[n];
                int mat = m >> 12;
                int rb_ = (m >> 6) & 63;
                int cb_ = m & 63;
                int ii  = n >> 4;
                int jj  = n & 15;
                OUT[(size_t)mat * (D * D) + (size_t)(rb_ * 16 + ii) * D
                    + (cb_ * 16 + jj)] = v;
            } else if (EPI == EPI_RESID) {
                OUT[(size_t)m * N + n] += 0.1f * v;
            } else { // EPI_RESID_SILU
                OUT[(size_t)m * N + n] += 0.1f * siluf(v);
            }
        }
    }
}

// --------------------------------- driver -----------------------------------
extern "C" void kernel_launch(void* const* d_in, const int* in_sizes, int n_in,
                              void* d_out, int out_size) {
    const int*   tokens = (const int*)d_in[0];
    const float* embed  = (const float*)d_in[1];
    const float* lmhead = (const float*)d_in[2];
    const float* finw   = (const float*)d_in[3];
    const float* n1w    = (const float*)d_in[4];
    const float* n2w    = (const float*)d_in[5];
    const float* w0     = (const float*)d_in[6];
    const float* b0     = (const float*)d_in[7];
    const float* w1     = (const float*)d_in[8];
    const float* b1     = (const float*)d_in[9];
    const float* w2     = (const float*)d_in[10];
    const float* b2     = (const float*)d_in[11];
    const float* w3     = (const float*)d_in[12];
    const float* b3     = (const float*)d_in[13];
    float* out = (float*)d_out;

    float *pX, *pH, *pW, *pG0, *pG1, *pENC, *pW0P;
    cudaGetSymbolAddress((void**)&pX,   g_X);
    cudaGetSymbolAddress((void**)&pH,   g_H);
    cudaGetSymbolAddress((void**)&pW,   g_W);
    cudaGetSymbolAddress((void**)&pG0,  g_G0);
    cudaGetSymbolAddress((void**)&pG1,  g_G1);
    cudaGetSymbolAddress((void**)&pENC, g_ENC);
    cudaGetSymbolAddress((void**)&pW0P, g_W0P);

    // --- embed gather + generator input encoding ---
    k_gather<<<NTOK, 256>>>(tokens, embed);
    k_padw0<<<GH, ENC_K>>>(w0);
    k_encode<<<(NROWS * ENC_K + 255) / 256, 256>>>();

    // --- generate all 16 weight matrices in one batched MLP pass ---
    dim3 gg(GH / 128, NROWS / 128);   // (2, 512)
    k_sgemm<EPI_SILU><<<gg, 256>>>(pENC, pW0P, b0, pG0, NROWS, GH, ENC_K);
    k_sgemm<EPI_SILU><<<gg, 256>>>(pG0,  w1,   b1, pG1, NROWS, GH, GH);
    k_sgemm<EPI_SILU><<<gg, 256>>>(pG1,  w2,   b2, pG0, NROWS, GH, GH);
    k_sgemm<EPI_GENW><<<gg, 256>>>(pG0,  w3,   b3, pW,  NROWS, GH, GH);

    // --- 8 transformer layers ---
    dim3 gl(D / 128, NTOK / 128);     // (8, 32)
    for (int li = 0; li < NLAYERS; li++) {
        k_rmsnorm<<<NTOK, 256>>>(pX, n1w + (size_t)li * D, pH);
        k_sgemm<EPI_RESID><<<gl, 256>>>(
            pH, pW + (size_t)(2 * li) * D * D, nullptr, pX, NTOK, D, D);
        k_rmsnorm<<<NTOK, 256>>>(pX, n2w + (size_t)li * D, pH);
        k_sgemm<EPI_RESID_SILU><<<gl, 256>>>(
            pH, pW + (size_t)(2 * li + 1) * D * D, nullptr, pX, NTOK, D, D);
    }

    // --- final norm + LM head ---
    k_rmsnorm<<<NTOK, 256>>>(pX, finw, pH);
    dim3 gf(VOCAB / 128, NTOK / 128); // (250, 32)
    k_sgemm<EPI_STORE><<<gf, 256>>>(pH, lmhead, nullptr, out, NTOK, VOCAB, D);
}

// round 10
// speedup vs baseline: 1.0105x; 1.0105x over previous
#include <cuda_runtime.h>
#include <math.h>
#include <stdint.h>

// ---------------------------------------------------------------------------
// GWEModel: tokens -> embed -> 8x[rmsnorm, x+=0.1*(h@W.T), rmsnorm,
//           x+=0.1*silu(h@Wffn.T)] -> rmsnorm -> lm_head
// All GEMMs are NT-SGEMMs using Blackwell packed fma.rn.f32x2 (FFMA2):
// 2 fp32 MACs per issued instruction, exact fp32 arithmetic.
// ---------------------------------------------------------------------------

#define D       1024
#define NLAYERS 8
#define VOCAB   32000
#define BSZ     16
#define GH      256
#define NFREQS  6
#define NTOK    4096
#define NB      64
#define NMAT    16
#define NROWS   (NMAT * NB * NB)   // 65536 generator rows
#define ENC_K   64                 // 52 features padded to 64
#define EPSV    1.1920929e-07f

// ------------------------- scratch (device globals) ------------------------
__device__ float g_X[NTOK * D];
__device__ float g_H[NTOK * D];
__device__ float g_W[(size_t)NMAT * D * D];
__device__ float g_G0[(size_t)NROWS * GH];
__device__ float g_G1[(size_t)NROWS * GH];
__device__ float g_ENC[(size_t)NROWS * ENC_K];
__device__ float g_W0P[GH * ENC_K];

// ------------------------------ tiny kernels -------------------------------
__global__ void k_gather(const int* __restrict__ tok,
                         const float* __restrict__ emb) {
    int t  = blockIdx.x;
    int tk = tok[t];
    const float4* src = (const float4*)(emb + (size_t)tk * D);
    float4*       dst = (float4*)(g_X + (size_t)t * D);
    dst[threadIdx.x] = src[threadIdx.x];
}

__global__ void k_padw0(const float* __restrict__ w0) {
    int g = blockIdx.x;
    int f = threadIdx.x;
    g_W0P[g * ENC_K + f] = (f < 52) ? w0[g * 52 + f] : 0.0f;
}

__global__ void k_encode() {
    int idx = blockIdx.x * blockDim.x + threadIdx.x;
    if (idx >= NROWS * ENC_K) return;
    int row = idx >> 6;
    int f   = idx & 63;
    float val = 0.0f;
    if (f < 52) {
        int   mat = row >> 12;
        int   blk = row & 4095;
        float c0  = (float)(mat >> 1) * (1.0f / 7.0f);
        float c1  = (float)(blk >> 6) * (1.0f / 63.0f);
        float c2  = (float)(blk & 63) * (1.0f / 63.0f);
        float c3  = (mat & 1) ? 0.5f : 0.0f;
        float coords[4] = {c0, c1, c2, c3};
        if (f < 4) {
            val = coords[f];
        } else {
            int   q = f - 4;
            int   g = q >> 3;
            int   r = q & 7;
            float a = (float)(1 << g) * 3.14159265358979f * coords[r & 3];
            val = (r >= 4) ? cosf(a) : sinf(a);
        }
    }
    g_ENC[idx] = val;
}

__global__ void k_rmsnorm(const float* __restrict__ x,
                          const float* __restrict__ w,
                          float* __restrict__ h) {
    int t   = threadIdx.x;
    int row = blockIdx.x;
    const float4* xr = (const float4*)(x + (size_t)row * D);
    float4 a = xr[t];
    float  s = a.x * a.x + a.y * a.y + a.z * a.z + a.w * a.w;
    #pragma unroll
    for (int o = 16; o > 0; o >>= 1) s += __shfl_xor_sync(0xffffffffu, s, o);
    __shared__ float sm[8];
    if ((t & 31) == 0) sm[t >> 5] = s;
    __syncthreads();
    float tot = 0.0f;
    #pragma unroll
    for (int i = 0; i < 8; i++) tot += sm[i];
    float inv = rsqrtf(tot * (1.0f / 1024.0f) + EPSV);
    float4 wv = ((const float4*)w)[t];
    float4 o;
    o.x = a.x * inv * wv.x; o.y = a.y * inv * wv.y;
    o.z = a.z * inv * wv.z; o.w = a.w * inv * wv.w;
    ((float4*)(h + (size_t)row * D))[t] = o;
}

// ------------------------------ SGEMM (NT, FFMA2) ---------------------------
// C[M,N] = A[M,K] @ B[N,K]^T, 128x128 tile, BK=16, 256 threads, 8x8/thread.
// Accumulators are packed f32x2 pairs along N: 32 fma.rn.f32x2 per k-step.
enum { EPI_STORE = 0, EPI_SILU = 1, EPI_GENW = 2, EPI_RESID = 3, EPI_RESID_SILU = 4 };

__device__ __forceinline__ float siluf(float v) {
    return v / (1.0f + __expf(-v));
}

template <int EPI>
__global__ __launch_bounds__(256)
void k_sgemm(const float* __restrict__ A, const float* __restrict__ B,
             const float* __restrict__ bias, float* __restrict__ OUT,
             int M, int N, int K) {
    __shared__ float As[16][128];
    __shared__ float Bs[16][128];
    const int tid = threadIdx.x;
    const int tx  = tid & 15;      // 0..15 -> N
    const int ty  = tid >> 4;      // 0..15 -> M
    const int bm  = blockIdx.y * 128;
    const int bn  = blockIdx.x * 128;
    const float* Ab = A + (size_t)bm * K;
    const float* Bb = B + (size_t)bn * K;

    unsigned long long acc[8][4];
    #pragma unroll
    for (int i = 0; i < 8; i++)
        #pragma unroll
        for (int j = 0; j < 4; j++) acc[i][j] = 0ull;

    for (int k0 = 0; k0 < K; k0 += 16) {
        #pragma unroll
        for (int it = 0; it < 2; it++) {
            int idx = tid + it * 256;
            int r   = idx >> 2;            // 0..127 tile row
            int c   = (idx & 3) << 2;      // 0,4,8,12 k-offset
            float4 va = *(const float4*)(Ab + (size_t)r * K + k0 + c);
            As[c + 0][r] = va.x; As[c + 1][r] = va.y;
            As[c + 2][r] = va.z; As[c + 3][r] = va.w;
            float4 vb = *(const float4*)(Bb + (size_t)r * K + k0 + c);
            Bs[c + 0][r] = vb.x; Bs[c + 1][r] = vb.y;
            Bs[c + 2][r] = vb.z; Bs[c + 3][r] = vb.w;
        }
        __syncthreads();
        #pragma unroll
        for (int k = 0; k < 16; k++) {
            float ra[8];
            *(float4*)(ra)     = *(const float4*)&As[k][ty * 8];
            *(float4*)(ra + 4) = *(const float4*)&As[k][ty * 8 + 4];
            unsigned long long rb[4];
            {
                ulonglong2 t0 = *(const ulonglong2*)&Bs[k][tx * 8];
                ulonglong2 t1 = *(const ulonglong2*)&Bs[k][tx * 8 + 4];
                rb[0] = t0.x; rb[1] = t0.y; rb[2] = t1.x; rb[3] = t1.y;
            }
            #pragma unroll
            for (int i = 0; i < 8; i++) {
                unsigned long long aa;
                asm("mov.b64 %0, {%1, %1};" : "=l"(aa) : "f"(ra[i]));
                #pragma unroll
                for (int j = 0; j < 4; j++) {
                    asm("fma.rn.f32x2 %0, %1, %2, %0;"
                        : "+l"(acc[i][j]) : "l"(aa), "l"(rb[j]));
                }
            }
        }
        __syncthreads();
    }

    // ------------------------------ epilogue --------------------------------
    #pragma unroll
    for (int i = 0; i < 8; i++) {
        int m = bm + ty * 8 + i;
        #pragma unroll
        for (int j = 0; j < 4; j++) {
            float vlo, vhi;
            asm("mov.b64 {%0, %1}, %2;" : "=f"(vlo), "=f"(vhi) : "l"(acc[i][j]));
            int n0 = bn + tx * 8 + 2 * j;       // even; pair is contiguous
            if (EPI == EPI_STORE) {
                *(float2*)&OUT[(size_t)m * N + n0] = make_float2(vlo, vhi);
            } else if (EPI == EPI_SILU) {
                float2 bb = *(const float2*)&bias[n0];
                *(float2*)&OUT[(size_t)m * N + n0] =
                    make_float2(siluf(vlo + bb.x), siluf(vhi + bb.y));
            } else if (EPI == EPI_GENW) {
                float2 bb = *(const float2*)&bias[n0];
                int mat = m >> 12;
                int rb_ = (m >> 6) & 63;
                int cb_ = m & 63;
                int ii  = n0 >> 4;
                int jj  = n0 & 15;  // even; jj+1 stays inside the 16-block
                float2* dst = (float2*)&g_W[(size_t)mat * (D * D)
                    + (size_t)(rb_ * 16 + ii) * D + (cb_ * 16 + jj)];
                *dst = make_float2(vlo + bb.x, vhi + bb.y);
            } else if (EPI == EPI_RESID) {
                float2* dst = (float2*)&OUT[(size_t)m * N + n0];
                float2 cur = *dst;
                *dst = make_float2(cur.x + 0.1f * vlo, cur.y + 0.1f * vhi);
            } else { // EPI_RESID_SILU
                float2* dst = (float2*)&OUT[(size_t)m * N + n0];
                float2 cur = *dst;
                *dst = make_float2(cur.x + 0.1f * siluf(vlo),
                                   cur.y + 0.1f * siluf(vhi));
            }
        }
    }
}

// --------------------------------- driver -----------------------------------
extern "C" void kernel_launch(void* const* d_in, const int* in_sizes, int n_in,
                              void* d_out, int out_size) {
    const int*   tokens = (const int*)d_in[0];
    const float* embed  = (const float*)d_in[1];
    const float* lmhead = (const float*)d_in[2];
    const float* finw   = (const float*)d_in[3];
    const float* n1w    = (const float*)d_in[4];
    const float* n2w    = (const float*)d_in[5];
    const float* w0     = (const float*)d_in[6];
    const float* b0     = (const float*)d_in[7];
    const float* w1     = (const float*)d_in[8];
    const float* b1     = (const float*)d_in[9];
    const float* w2     = (const float*)d_in[10];
    const float* b2     = (const float*)d_in[11];
    const float* w3     = (const float*)d_in[12];
    const float* b3     = (const float*)d_in[13];
    float* out = (float*)d_out;

    float *pX, *pH, *pW, *pG0, *pG1, *pENC, *pW0P;
    cudaGetSymbolAddress((void**)&pX,   g_X);
    cudaGetSymbolAddress((void**)&pH,   g_H);
    cudaGetSymbolAddress((void**)&pW,   g_W);
    cudaGetSymbolAddress((void**)&pG0,  g_G0);
    cudaGetSymbolAddress((void**)&pG1,  g_G1);
    cudaGetSymbolAddress((void**)&pENC, g_ENC);
    cudaGetSymbolAddress((void**)&pW0P, g_W0P);

    // --- embed gather + generator input encoding ---
    k_gather<<<NTOK, 256>>>(tokens, embed);
    k_padw0<<<GH, ENC_K>>>(w0);
    k_encode<<<(NROWS * ENC_K + 255) / 256, 256>>>();

    // --- generate all 16 weight matrices in one batched MLP pass ---
    dim3 gg(GH / 128, NROWS / 128);   // (2, 512)
    k_sgemm<EPI_SILU><<<gg, 256>>>(pENC, pW0P, b0, pG0, NROWS, GH, ENC_K);
    k_sgemm<EPI_SILU><<<gg, 256>>>(pG0,  w1,   b1, pG1, NROWS, GH, GH);
    k_sgemm<EPI_SILU><<<gg, 256>>>(pG1,  w2,   b2, pG0, NROWS, GH, GH);
    k_sgemm<EPI_GENW><<<gg, 256>>>(pG0,  w3,   b3, pW,  NROWS, GH, GH);

    // --- 8 transformer layers ---
    dim3 gl(D / 128, NTOK / 128);     // (8, 32)
    for (int li = 0; li < NLAYERS; li++) {
        k_rmsnorm<<<NTOK, 256>>>(pX, n1w + (size_t)li * D, pH);
        k_sgemm<EPI_RESID><<<gl, 256>>>(
            pH, pW + (size_t)(2 * li) * D * D, nullptr, pX, NTOK, D, D);
        k_rmsnorm<<<NTOK, 256>>>(pX, n2w + (size_t)li * D, pH);
        k_sgemm<EPI_RESID_SILU><<<gl, 256>>>(
            pH, pW + (size_t)(2 * li + 1) * D * D, nullptr, pX, NTOK, D, D);
    }

    // --- final norm + LM head ---
    k_rmsnorm<<<NTOK, 256>>>(pX, finw, pH);
    dim3 gf(VOCAB / 128, NTOK / 128); // (250, 32)
    k_sgemm<EPI_STORE><<<gf, 256>>>(pH, lmhead, nullptr, out, NTOK, VOCAB, D);
}

// round 11
// speedup vs baseline: 1.0131x; 1.0026x over previous
#include <cuda_runtime.h>
#include <math.h>
#include <stdint.h>

// ---------------------------------------------------------------------------
// GWEModel: tokens -> embed -> 8x[rmsnorm, x+=0.1*(h@W.T), rmsnorm,
//           x+=0.1*silu(h@Wffn.T)] -> rmsnorm -> lm_head
// All GEMMs are NT-SGEMMs using Blackwell packed fma.rn.f32x2 (FFMA2):
// 2 fp32 MACs per issued instruction, exact fp32 arithmetic.
// ---------------------------------------------------------------------------

#define D       1024
#define NLAYERS 8
#define VOCAB   32000
#define BSZ     16
#define GH      256
#define NFREQS  6
#define NTOK    4096
#define NB      64
#define NMAT    16
#define NROWS   (NMAT * NB * NB)   // 65536 generator rows
#define ENC_K   64                 // 52 features padded to 64
#define EPSV    1.1920929e-07f

// ------------------------- scratch (device globals) ------------------------
__device__ float g_X[NTOK * D];
__device__ float g_H[NTOK * D];
__device__ float g_W[(size_t)NMAT * D * D];
__device__ float g_G0[(size_t)NROWS * GH];
__device__ float g_G1[(size_t)NROWS * GH];
__device__ float g_ENC[(size_t)NROWS * ENC_K];
__device__ float g_W0P[GH * ENC_K];

// ------------------------------ tiny kernels -------------------------------
__global__ void k_gather(const int* __restrict__ tok,
                         const float* __restrict__ emb) {
    int t  = blockIdx.x;
    int tk = tok[t];
    const float4* src = (const float4*)(emb + (size_t)tk * D);
    float4*       dst = (float4*)(g_X + (size_t)t * D);
    dst[threadIdx.x] = src[threadIdx.x];
}

__global__ void k_padw0(const float* __restrict__ w0) {
    int g = blockIdx.x;
    int f = threadIdx.x;
    g_W0P[g * ENC_K + f] = (f < 52) ? w0[g * 52 + f] : 0.0f;
}

__global__ void k_encode() {
    int idx = blockIdx.x * blockDim.x + threadIdx.x;
    if (idx >= NROWS * ENC_K) return;
    int row = idx >> 6;
    int f   = idx & 63;
    float val = 0.0f;
    if (f < 52) {
        int   mat = row >> 12;
        int   blk = row & 4095;
        float c0  = (float)(mat >> 1) * (1.0f / 7.0f);
        float c1  = (float)(blk >> 6) * (1.0f / 63.0f);
        float c2  = (float)(blk & 63) * (1.0f / 63.0f);
        float c3  = (mat & 1) ? 0.5f : 0.0f;
        float coords[4] = {c0, c1, c2, c3};
        if (f < 4) {
            val = coords[f];
        } else {
            int   q = f - 4;
            int   g = q >> 3;
            int   r = q & 7;
            float a = (float)(1 << g) * 3.14159265358979f * coords[r & 3];
            val = (r >= 4) ? cosf(a) : sinf(a);
        }
    }
    g_ENC[idx] = val;
}

__global__ void k_rmsnorm(const float* __restrict__ x,
                          const float* __restrict__ w,
                          float* __restrict__ h) {
    int t   = threadIdx.x;
    int row = blockIdx.x;
    const float4* xr = (const float4*)(x + (size_t)row * D);
    float4 a = xr[t];
    float  s = a.x * a.x + a.y * a.y + a.z * a.z + a.w * a.w;
    #pragma unroll
    for (int o = 16; o > 0; o >>= 1) s += __shfl_xor_sync(0xffffffffu, s, o);
    __shared__ float sm[8];
    if ((t & 31) == 0) sm[t >> 5] = s;
    __syncthreads();
    float tot = 0.0f;
    #pragma unroll
    for (int i = 0; i < 8; i++) tot += sm[i];
    float inv = rsqrtf(tot * (1.0f / 1024.0f) + EPSV);
    float4 wv = ((const float4*)w)[t];
    float4 o;
    o.x = a.x * inv * wv.x; o.y = a.y * inv * wv.y;
    o.z = a.z * inv * wv.z; o.w = a.w * inv * wv.w;
    ((float4*)(h + (size_t)row * D))[t] = o;
}

// ------------------------------ SGEMM (NT, FFMA2) ---------------------------
// C[M,N] = A[M,K] @ B[N,K]^T, 128x128 tile, BK=16, 256 threads, 8x8/thread.
// Accumulators are packed f32x2 pairs along N: 32 fma.rn.f32x2 per k-step.
enum { EPI_STORE = 0, EPI_SILU = 1, EPI_GENW = 2, EPI_RESID = 3, EPI_RESID_SILU = 4 };

__device__ __forceinline__ float siluf(float v) {
    return v / (1.0f + __expf(-v));
}

template <int EPI>
__global__ __launch_bounds__(256)
void k_sgemm(const float* __restrict__ A, const float* __restrict__ B,
             const float* __restrict__ bias, float* __restrict__ OUT,
             int M, int N, int K) {
    __shared__ float As[16][128];
    __shared__ float Bs[16][128];
    const int tid = threadIdx.x;
    const int tx  = tid & 15;      // 0..15 -> N
    const int ty  = tid >> 4;      // 0..15 -> M
    const int bm  = blockIdx.y * 128;
    const int bn  = blockIdx.x * 128;
    const float* Ab = A + (size_t)bm * K;
    const float* Bb = B + (size_t)bn * K;

    unsigned long long acc[8][4];
    #pragma unroll
    for (int i = 0; i < 8; i++)
        #pragma unroll
        for (int j = 0; j < 4; j++) acc[i][j] = 0ull;

    for (int k0 = 0; k0 < K; k0 += 16) {
        #pragma unroll
        for (int it = 0; it < 2; it++) {
            int idx = tid + it * 256;
            int r   = idx >> 2;            // 0..127 tile row
            int c   = (idx & 3) << 2;      // 0,4,8,12 k-offset
            float4 va = *(const float4*)(Ab + (size_t)r * K + k0 + c);
            As[c + 0][r] = va.x; As[c + 1][r] = va.y;
            As[c + 2][r] = va.z; As[c + 3][r] = va.w;
            float4 vb = *(const float4*)(Bb + (size_t)r * K + k0 + c);
            Bs[c + 0][r] = vb.x; Bs[c + 1][r] = vb.y;
            Bs[c + 2][r] = vb.z; Bs[c + 3][r] = vb.w;
        }
        __syncthreads();
        #pragma unroll
        for (int k = 0; k < 16; k++) {
            float ra[8];
            *(float4*)(ra)     = *(const float4*)&As[k][ty * 8];
            *(float4*)(ra + 4) = *(const float4*)&As[k][ty * 8 + 4];
            unsigned long long rb[4];
            {
                ulonglong2 t0 = *(const ulonglong2*)&Bs[k][tx * 8];
                ulonglong2 t1 = *(const ulonglong2*)&Bs[k][tx * 8 + 4];
                rb[0] = t0.x; rb[1] = t0.y; rb[2] = t1.x; rb[3] = t1.y;
            }
            #pragma unroll
            for (int i = 0; i < 8; i++) {
                unsigned long long aa;
                asm("mov.b64 %0, {%1, %1};" : "=l"(aa) : "f"(ra[i]));
                #pragma unroll
                for (int j = 0; j < 4; j++) {
                    asm("fma.rn.f32x2 %0, %1, %2, %0;"
                        : "+l"(acc[i][j]) : "l"(aa), "l"(rb[j]));
                }
            }
        }
        __syncthreads();
    }

    // ------------------------------ epilogue --------------------------------
    #pragma unroll
    for (int i = 0; i < 8; i++) {
        int m = bm + ty * 8 + i;
        #pragma unroll
        for (int j = 0; j < 4; j++) {
            float vlo, vhi;
            asm("mov.b64 {%0, %1}, %2;" : "=f"(vlo), "=f"(vhi) : "l"(acc[i][j]));
            int n0 = bn + tx * 8 + 2 * j;       // even; pair is contiguous
            if (EPI == EPI_STORE) {
                *(float2*)&OUT[(size_t)m * N + n0] = make_float2(vlo, vhi);
            } else if (EPI == EPI_SILU) {
                float2 bb = *(const float2*)&bias[n0];
                *(float2*)&OUT[(size_t)m * N + n0] =
                    make_float2(siluf(vlo + bb.x), siluf(vhi + bb.y));
            } else if (EPI == EPI_GENW) {
                float2 bb = *(const float2*)&bias[n0];
                int mat = m >> 12;
                int rb_ = (m >> 6) & 63;
                int cb_ = m & 63;
                int ii  = n0 >> 4;
                int jj  = n0 & 15;  // even; jj+1 stays inside the 16-block
                float2* dst = (float2*)&g_W[(size_t)mat * (D * D)
                    + (size_t)(rb_ * 16 + ii) * D + (cb_ * 16 + jj)];
                *dst = make_float2(vlo + bb.x, vhi + bb.y);
            } else if (EPI == EPI_RESID) {
                float2* dst = (float2*)&OUT[(size_t)m * N + n0];
                float2 cur = *dst;
                *dst = make_float2(cur.x + 0.1f * vlo, cur.y + 0.1f * vhi);
            } else { // EPI_RESID_SILU
                float2* dst = (float2*)&OUT[(size_t)m * N + n0];
                float2 cur = *dst;
                *dst = make_float2(cur.x + 0.1f * siluf(vlo),
                                   cur.y + 0.1f * siluf(vhi));
            }
        }
    }
}

// --------------------------------- driver -----------------------------------
extern "C" void kernel_launch(void* const* d_in, const int* in_sizes, int n_in,
                              void* d_out, int out_size) {
    const int*   tokens = (const int*)d_in[0];
    const float* embed  = (const float*)d_in[1];
    const float* lmhead = (const float*)d_in[2];
    const float* finw   = (const float*)d_in[3];
    const float* n1w    = (const float*)d_in[4];
    const float* n2w    = (const float*)d_in[5];
    const float* w0     = (const float*)d_in[6];
    const float* b0     = (const float*)d_in[7];
    const float* w1     = (const float*)d_in[8];
    const float* b1     = (const float*)d_in[9];
    const float* w2     = (const float*)d_in[10];
    const float* b2     = (const float*)d_in[11];
    const float* w3     = (const float*)d_in[12];
    const float* b3     = (const float*)d_in[13];
    float* out = (float*)d_out;

    float *pX, *pH, *pW, *pG0, *pG1, *pENC, *pW0P;
    cudaGetSymbolAddress((void**)&pX,   g_X);
    cudaGetSymbolAddress((void**)&pH,   g_H);
    cudaGetSymbolAddress((void**)&pW,   g_W);
    cudaGetSymbolAddress((void**)&pG0,  g_G0);
    cudaGetSymbolAddress((void**)&pG1,  g_G1);
    cudaGetSymbolAddress((void**)&pENC, g_ENC);
    cudaGetSymbolAddress((void**)&pW0P, g_W0P);

    // --- embed gather + generator input encoding ---
    k_gather<<<NTOK, 256>>>(tokens, embed);
    k_padw0<<<GH, ENC_K>>>(w0);
    k_encode<<<(NROWS * ENC_K + 255) / 256, 256>>>();

    // --- generate all 16 weight matrices in one batched MLP pass ---
    dim3 gg(GH / 128, NROWS / 128);   // (2, 512)
    k_sgemm<EPI_SILU><<<gg, 256>>>(pENC, pW0P, b0, pG0, NROWS, GH, ENC_K);
    k_sgemm<EPI_SILU><<<gg, 256>>>(pG0,  w1,   b1, pG1, NROWS, GH, GH);
    k_sgemm<EPI_SILU><<<gg, 256>>>(pG1,  w2,   b2, pG0, NROWS, GH, GH);
    k_sgemm<EPI_GENW><<<gg, 256>>>(pG0,  w3,   b3, pW,  NROWS, GH, GH);

    // --- 8 transformer layers ---
    dim3 gl(D / 128, NTOK / 128);     // (8, 32)
    for (int li = 0; li < NLAYERS; li++) {
        k_rmsnorm<<<NTOK, 256>>>(pX, n1w + (size_t)li * D, pH);
        k_sgemm<EPI_RESID><<<gl, 256>>>(
            pH, pW + (size_t)(2 * li) * D * D, nullptr, pX, NTOK, D, D);
        k_rmsnorm<<<NTOK, 256>>>(pX, n2w + (size_t)li * D, pH);
        k_sgemm<EPI_RESID_SILU><<<gl, 256>>>(
            pH, pW + (size_t)(2 * li + 1) * D * D, nullptr, pX, NTOK, D, D);
    }

    // --- final norm + LM head ---
    k_rmsnorm<<<NTOK, 256>>>(pX, finw, pH);
    dim3 gf(VOCAB / 128, NTOK / 128); // (250, 32)
    k_sgemm<EPI_STORE><<<gf, 256>>>(pH, lmhead, nullptr, out, NTOK, VOCAB, D);
}